// round 11
// baseline (speedup 1.0000x reference)
#include <cuda_runtime.h>
#include <mma.h>
#include <cstdint>

using namespace nvcuda;

#define HID    1024
#define NHEADS 16
#define HDIM   64
#define BATCH  8
#define SEQ    1024
#define MROWS  (BATCH*SEQ)        // 8192
#define BHS    (BATCH*NHEADS*SEQ) // 131072

// Scratch (device globals — no allocation allowed)
__device__ float g_Q[MROWS*HID];
__device__ float g_K[MROWS*HID];
__device__ float g_V[MROWS*HID];
__device__ float g_O[MROWS*HID];
// tf32-rounded copies of GEMM operands
__device__ float g_Rq[MROWS*HID];
__device__ float g_Rk[MROWS*HID];
__device__ float g_Rv[MROWS*HID];
__device__ float g_Wq[HID*HID];
__device__ float g_Wk[HID*HID];
__device__ float g_Wv[HID*HID];
__device__ float g_Wo[HID*HID];

// ---------------------------------------------------------------------------
// cp.async helpers
// ---------------------------------------------------------------------------
__device__ __forceinline__ void cp_async16(void* smem, const void* gmem){
    unsigned s = (unsigned)__cvta_generic_to_shared(smem);
    asm volatile("cp.async.cg.shared.global [%0], [%1], 16;\n" :: "r"(s), "l"(gmem));
}
#define CP_COMMIT()  asm volatile("cp.async.commit_group;\n" ::: "memory")
#define CP_WAIT0()   asm volatile("cp.async.wait_group 0;\n" ::: "memory")

// ---------------------------------------------------------------------------
// tf32 pre-rounding kernels: out[i] = round_tf32(in[i])
// ---------------------------------------------------------------------------
__global__ void __launch_bounds__(256)
round_act_kernel(const float* __restrict__ a0, const float* __restrict__ a1,
                 const float* __restrict__ a2,
                 float* __restrict__ o0, float* __restrict__ o1,
                 float* __restrict__ o2)
{
    const int z = blockIdx.z;
    const float* in  = (z==0) ? a0 : (z==1) ? a1 : a2;
    float*       out = (z==0) ? o0 : (z==1) ? o1 : o2;
    size_t i = ((size_t)blockIdx.x * 256 + threadIdx.x) * 4;
    float4 v = *(const float4*)(in + i);
    v.x = wmma::__float_to_tf32(v.x);
    v.y = wmma::__float_to_tf32(v.y);
    v.z = wmma::__float_to_tf32(v.z);
    v.w = wmma::__float_to_tf32(v.w);
    *(float4*)(out + i) = v;
}

__global__ void __launch_bounds__(256)
round_w_kernel(const float* __restrict__ w0, const float* __restrict__ w1,
               const float* __restrict__ w2, const float* __restrict__ w3,
               float* __restrict__ o0, float* __restrict__ o1,
               float* __restrict__ o2, float* __restrict__ o3)
{
    const int z = blockIdx.z;
    const float* in  = (z==0) ? w0 : (z==1) ? w1 : (z==2) ? w2 : w3;
    float*       out = (z==0) ? o0 : (z==1) ? o1 : (z==2) ? o2 : o3;
    size_t i = ((size_t)blockIdx.x * 256 + threadIdx.x) * 4;
    float4 v = *(const float4*)(in + i);
    v.x = wmma::__float_to_tf32(v.x);
    v.y = wmma::__float_to_tf32(v.y);
    v.z = wmma::__float_to_tf32(v.z);
    v.w = wmma::__float_to_tf32(v.w);
    *(float4*)(out + i) = v;
}

// ===========================================================================
// Projection body: C[M,1024] = (A[M,1024] @ W[1024,1024]^T + bias) * scale
// A and W are PRE-ROUNDED to tf32 -> no conversions in the inner loop.
// If rnd_store, output is tf32-rounded at store (feeds later tensor ops).
// ===========================================================================
#define TBM 128
#define TBN 128
#define TBK 32
#define LDT 36
#define PROJ_BUF (TBM*LDT)
#define PROJ_SMEM_FLOATS (4*PROJ_BUF)
#define PROJ_SMEM_BYTES (PROJ_SMEM_FLOATS*4)   // 73728
#define EPLD 132

__device__ __forceinline__
void proj_body(const float* __restrict__ A, const float* __restrict__ W,
               const float* __restrict__ bias, float scale, float* __restrict__ C,
               float* sm, bool rnd_store)
{
    float* Asb[2] = { sm,              sm + 2*PROJ_BUF };
    float* Bsb[2] = { sm + PROJ_BUF,   sm + 3*PROJ_BUF };

    const int tid  = threadIdx.x;
    const int warp = tid >> 5;
    const int wm   = warp & 3;
    const int wn   = warp >> 2;
    const int m0   = blockIdx.y * TBM;
    const int n0   = blockIdx.x * TBN;

    wmma::fragment<wmma::accumulator,16,16,8,float> acc[2][4];
    #pragma unroll
    for (int mi=0;mi<2;mi++)
        #pragma unroll
        for (int ni=0;ni<4;ni++)
            wmma::fill_fragment(acc[mi][ni], 0.0f);

    const int lr  = tid >> 3;
    const int lc4 = (tid & 7) * 4;

    {
        #pragma unroll
        for (int p=0;p<4;p++){
            int r = p*32 + lr;
            cp_async16(Asb[0] + r*LDT + lc4, A + (size_t)(m0 + r)*HID + lc4);
            cp_async16(Bsb[0] + r*LDT + lc4, W + (size_t)(n0 + r)*HID + lc4);
        }
        CP_COMMIT();
    }

    const int NKT = HID / TBK;  // 32
    for (int kt=0; kt<NKT; kt++){
        CP_WAIT0();
        __syncthreads();
        if (kt+1 < NKT){
            const int k0 = (kt+1)*TBK;
            float* Ad = Asb[(kt+1)&1];
            float* Bd = Bsb[(kt+1)&1];
            #pragma unroll
            for (int p=0;p<4;p++){
                int r = p*32 + lr;
                cp_async16(Ad + r*LDT + lc4, A + (size_t)(m0 + r)*HID + k0 + lc4);
                cp_async16(Bd + r*LDT + lc4, W + (size_t)(n0 + r)*HID + k0 + lc4);
            }
            CP_COMMIT();
        }
        const float* As = Asb[kt&1];
        const float* Bs = Bsb[kt&1];
        #pragma unroll
        for (int kk=0; kk<TBK; kk+=8){
            wmma::fragment<wmma::matrix_a,16,16,8,wmma::precision::tf32,wmma::row_major> af[2];
            wmma::fragment<wmma::matrix_b,16,16,8,wmma::precision::tf32,wmma::col_major> bf[4];
            #pragma unroll
            for (int mi=0;mi<2;mi++)
                wmma::load_matrix_sync(af[mi], As + (wm*32+mi*16)*LDT + kk, LDT);
            #pragma unroll
            for (int ni=0;ni<4;ni++)
                wmma::load_matrix_sync(bf[ni], Bs + (wn*64+ni*16)*LDT + kk, LDT);
            #pragma unroll
            for (int mi=0;mi<2;mi++)
                #pragma unroll
                for (int ni=0;ni<4;ni++)
                    wmma::mma_sync(acc[mi][ni], af[mi], bf[ni], acc[mi][ni]);
        }
    }

    __syncthreads();
    #pragma unroll
    for (int mi=0;mi<2;mi++)
        #pragma unroll
        for (int ni=0;ni<4;ni++)
            wmma::store_matrix_sync(sm + (wm*32+mi*16)*EPLD + wn*64 + ni*16,
                                    acc[mi][ni], EPLD, wmma::mem_row_major);
    __syncthreads();
    {
        const int er  = tid >> 5;
        const int ec4 = (tid & 31) * 4;
        float4 bb = *(const float4*)(bias + n0 + ec4);
        #pragma unroll
        for (int p=0;p<16;p++){
            int r = p*8 + er;
            float4 v = *(float4*)(sm + r*EPLD + ec4);
            v.x = (v.x + bb.x) * scale;
            v.y = (v.y + bb.y) * scale;
            v.z = (v.z + bb.z) * scale;
            v.w = (v.w + bb.w) * scale;
            if (rnd_store){
                v.x = wmma::__float_to_tf32(v.x);
                v.y = wmma::__float_to_tf32(v.y);
                v.z = wmma::__float_to_tf32(v.z);
                v.w = wmma::__float_to_tf32(v.w);
            }
            *(float4*)(C + (size_t)(m0 + r)*HID + n0 + ec4) = v;
        }
    }
}

// Merged Q/K/V projection: blockIdx.z selects which projection
__global__ void __launch_bounds__(256,2)
qkv_proj_kernel(const float* __restrict__ q, const float* __restrict__ k,
                const float* __restrict__ v,
                const float* __restrict__ Wq, const float* __restrict__ Wk,
                const float* __restrict__ Wv,
                const float* __restrict__ bq, const float* __restrict__ bk,
                const float* __restrict__ bv,
                float* __restrict__ qo, float* __restrict__ ko, float* __restrict__ vo)
{
    extern __shared__ float sm[];
    const int z = blockIdx.z;
    const float* A    = (z==0) ? q  : (z==1) ? k  : v;
    const float* W    = (z==0) ? Wq : (z==1) ? Wk : Wv;
    const float* bias = (z==0) ? bq : (z==1) ? bk : bv;
    float*       C    = (z==0) ? qo : (z==1) ? ko : vo;
    const float scale = (z==0) ? 0.125f : 1.0f;
    proj_body(A, W, bias, scale, C, sm, true);   // outputs feed tensor ops -> round
}

__global__ void __launch_bounds__(256,2)
proj_kernel(const float* __restrict__ A, const float* __restrict__ W,
            const float* __restrict__ bias, float scale, float* __restrict__ C)
{
    extern __shared__ float sm[];
    proj_body(A, W, bias, scale, C, sm, false);  // final output -> exact
}

// ===========================================================================
// Fused attention: per block = 32 query rows of one (b,h). 512 threads,
// two warp-groups of 8 warps with private double-buffered 64-col K/V chunks.
// Q/K/V are tf32-rounded at projection store -> no conversions in MMA loops.
// P is rounded once when written to the smem copy (gmem attention stays exact).
// ===========================================================================
#define STRIPE 32
#define CH     64
#define NCHUNK (SEQ/CH)           // 16
#define LDE    1032
#define LDK    72
#define LDQ    72
#define CHBUF  (CH*LDK)
#define FUSED_SMEM_FLOATS (STRIPE*LDE + STRIPE*LDQ + 4*CHBUF + SEQ)
#define FUSED_SMEM_BYTES  (FUSED_SMEM_FLOATS*4)   // 219136

__device__ __forceinline__ void bar_group(int grp){
    asm volatile("bar.sync %0, 256;" :: "r"(grp+1) : "memory");
}

__global__ void __launch_bounds__(512,1)
fused_attn_kernel(float* __restrict__ attn, const int* __restrict__ mask)
{
    extern __shared__ float smf[];
    float* Es  = smf;                      // 32 x 1032
    float* Qs  = Es + STRIPE*LDE;          // 32 x 72 (reused as O-reduce buffer)
    float* KVB = Qs + STRIPE*LDQ;          // 4 chunk buffers of 64 x 72
    int*   Ms  = (int*)(KVB + 4*CHBUF);    // 1024 ints

    const int tid   = threadIdx.x;
    const int warp  = tid >> 5;
    const int lane  = tid & 31;
    const int grp   = tid >> 8;
    const int gwarp = warp & 7;
    const int gtid  = tid & 255;

    const int blk  = blockIdx.x;
    const int bh   = blk >> 5;
    const int strp = blk & 31;
    const int b    = bh >> 4;
    const int h    = bh & 15;
    const int m0   = strp * STRIPE;

    const float* Qb = g_Q + ((size_t)b*SEQ + m0)*HID + h*HDIM;
    const float* Kb = g_K + (size_t)b*SEQ*HID + h*HDIM;
    const float* Vb = g_V + (size_t)b*SEQ*HID + h*HDIM;

    float* mybuf[2] = { KVB + (grp*2)*CHBUF, KVB + (grp*2+1)*CHBUF };

    if (tid < 256)
        *(int4*)(Ms + tid*4) = *(const int4*)(mask + b*SEQ + tid*4);

    {
        const int r  = tid >> 4;
        const int c4 = (tid & 15) * 4;
        cp_async16(Qs + r*LDQ + c4, Qb + (size_t)r*HID + c4);
    }
    {
        const int r  = gtid >> 4;
        const int c4 = (gtid & 15) * 4;
        const float* src = Kb + (size_t)(grp*CH)*HID;
        #pragma unroll
        for (int p=0;p<4;p++)
            cp_async16(mybuf[0] + (p*16+r)*LDK + c4, src + (size_t)(p*16+r)*HID + c4);
        CP_COMMIT();
    }
    // All threads wait own cp.asyncs, then FULL barrier (Q loaded cross-group).
    CP_WAIT0();
    __syncthreads();

    // -------- Phase 1: QK^T --------
    const int wm = gwarp & 1;
    const int wn = gwarp >> 1;
    for (int ci=0; ci<NCHUNK/2; ci++){
        const int c = 2*ci + grp;
        CP_WAIT0();
        bar_group(grp);
        if (ci+1 < NCHUNK/2){
            const int cn = c + 2;
            const float* src = Kb + (size_t)(cn*CH)*HID;
            float* dst = mybuf[(ci+1)&1];
            const int r  = gtid >> 4;
            const int c4 = (gtid & 15) * 4;
            #pragma unroll
            for (int p=0;p<4;p++)
                cp_async16(dst + (p*16+r)*LDK + c4, src + (size_t)(p*16+r)*HID + c4);
            CP_COMMIT();
        }
        const float* Ks = mybuf[ci&1];
        wmma::fragment<wmma::accumulator,16,16,8,float> a0, a1;
        wmma::fill_fragment(a0, 0.0f);
        wmma::fill_fragment(a1, 0.0f);
        #pragma unroll
        for (int k=0;k<HDIM;k+=16){
            wmma::fragment<wmma::matrix_a,16,16,8,wmma::precision::tf32,wmma::row_major> af0, af1;
            wmma::fragment<wmma::matrix_b,16,16,8,wmma::precision::tf32,wmma::col_major> bf0, bf1;
            wmma::load_matrix_sync(af0, Qs + (wm*16)*LDQ + k, LDQ);
            wmma::load_matrix_sync(af1, Qs + (wm*16)*LDQ + k + 8, LDQ);
            wmma::load_matrix_sync(bf0, Ks + (wn*16)*LDK + k, LDK);
            wmma::load_matrix_sync(bf1, Ks + (wn*16)*LDK + k + 8, LDK);
            wmma::mma_sync(a0, af0, bf0, a0);
            wmma::mma_sync(a1, af1, bf1, a1);
        }
        #pragma unroll
        for (int t=0;t<a0.num_elements;t++) a0.x[t] += a1.x[t];
        wmma::store_matrix_sync(Es + (wm*16)*LDE + c*CH + wn*16, a0, LDE,
                                wmma::mem_row_major);
    }

    {
        const float* src = Vb + (size_t)(grp*8*CH)*HID;
        const int r  = gtid >> 4;
        const int c4 = (gtid & 15) * 4;
        #pragma unroll
        for (int p=0;p<4;p++)
            cp_async16(mybuf[0] + (p*16+r)*LDK + c4, src + (size_t)(p*16+r)*HID + c4);
        CP_COMMIT();
    }
    __syncthreads();

    // -------- Phase 2: masked softmax, write P once --------
    #pragma unroll
    for (int rr=0; rr<2; rr++){
        const int r = warp*2 + rr;
        float v[32];
        float mx = -1e30f;
        #pragma unroll
        for (int i=0;i<8;i++){
            float4 t  = *(float4*)(Es + r*LDE + i*128 + lane*4);
            int4   mk = *(const int4*)(Ms + i*128 + lane*4);
            t.x = (mk.x == 0) ? -1e10f : t.x;
            t.y = (mk.y == 0) ? -1e10f : t.y;
            t.z = (mk.z == 0) ? -1e10f : t.z;
            t.w = (mk.w == 0) ? -1e10f : t.w;
            v[i*4+0]=t.x; v[i*4+1]=t.y; v[i*4+2]=t.z; v[i*4+3]=t.w;
            mx = fmaxf(mx, fmaxf(fmaxf(t.x,t.y), fmaxf(t.z,t.w)));
        }
        #pragma unroll
        for (int o=16;o;o>>=1) mx = fmaxf(mx, __shfl_xor_sync(0xffffffffu, mx, o));
        float s = 0.0f;
        #pragma unroll
        for (int i=0;i<32;i++){ v[i] = __expf(v[i]-mx); s += v[i]; }
        #pragma unroll
        for (int o=16;o;o>>=1) s += __shfl_xor_sync(0xffffffffu, s, o);
        const float inv = 1.0f / s;
        float* arow = attn + ((size_t)bh*SEQ + m0 + r) * SEQ;
        #pragma unroll
        for (int i=0;i<8;i++){
            float4 p;
            p.x = v[i*4+0]*inv; p.y = v[i*4+1]*inv;
            p.z = v[i*4+2]*inv; p.w = v[i*4+3]*inv;
            *(float4*)(arow + i*128 + lane*4) = p;   // exact attention output
            float4 pr;                                // rounded copy for PV MMA
            pr.x = wmma::__float_to_tf32(p.x);
            pr.y = wmma::__float_to_tf32(p.y);
            pr.z = wmma::__float_to_tf32(p.z);
            pr.w = wmma::__float_to_tf32(p.w);
            *(float4*)(Es + r*LDE + i*128 + lane*4) = pr;
        }
    }
    __syncthreads();

    // -------- Phase 3: O = P V, k split across groups --------
    wmma::fragment<wmma::accumulator,16,16,8,float> o0, o1;
    wmma::fill_fragment(o0, 0.0f);
    wmma::fill_fragment(o1, 0.0f);
    const int pn = gwarp >> 1;

    for (int ci=0; ci<8; ci++){
        CP_WAIT0();
        bar_group(grp);
        if (ci+1 < 8){
            const float* src = Vb + (size_t)(grp*8*CH + (ci+1)*CH)*HID;
            float* dst = mybuf[(ci+1)&1];
            const int r  = gtid >> 4;
            const int c4 = (gtid & 15) * 4;
            #pragma unroll
            for (int p=0;p<4;p++)
                cp_async16(dst + (p*16+r)*LDK + c4, src + (size_t)(p*16+r)*HID + c4);
            CP_COMMIT();
        }
        const float* Vs = mybuf[ci&1];
        const int kbase = grp*8*CH + ci*CH;
        #pragma unroll
        for (int kk=0; kk<CH; kk+=16){
            wmma::fragment<wmma::matrix_a,16,16,8,wmma::precision::tf32,wmma::row_major> af0, af1;
            wmma::fragment<wmma::matrix_b,16,16,8,wmma::precision::tf32,wmma::row_major> bf0, bf1;
            wmma::load_matrix_sync(af0, Es + (wm*16)*LDE + kbase + kk, LDE);
            wmma::load_matrix_sync(af1, Es + (wm*16)*LDE + kbase + kk + 8, LDE);
            wmma::load_matrix_sync(bf0, Vs + kk*LDK + pn*16, LDK);
            wmma::load_matrix_sync(bf1, Vs + (kk+8)*LDK + pn*16, LDK);
            wmma::mma_sync(o0, af0, bf0, o0);
            wmma::mma_sync(o1, af1, bf1, o1);
        }
    }
    #pragma unroll
    for (int t=0;t<o0.num_elements;t++) o0.x[t] += o1.x[t];

    if (grp == 1)
        wmma::store_matrix_sync(Qs + (wm*16)*LDQ + pn*16, o0, LDQ,
                                wmma::mem_row_major);
    __syncthreads();
    if (grp == 0){
        wmma::fragment<wmma::accumulator,16,16,8,float> part;
        wmma::load_matrix_sync(part, Qs + (wm*16)*LDQ + pn*16, LDQ,
                               wmma::mem_row_major);
        #pragma unroll
        for (int t=0;t<o0.num_elements;t++){
            o0.x[t] += part.x[t];
            o0.x[t] = wmma::__float_to_tf32(o0.x[t]);  // g_O feeds out-proj MMA
        }
        wmma::store_matrix_sync(g_O + (size_t)(b*SEQ + m0 + wm*16)*HID
                                    + h*HDIM + pn*16,
                                o0, HID, wmma::mem_row_major);
    }
}

// ---------------------------------------------------------------------------
extern "C" void kernel_launch(void* const* d_in, const int* in_sizes, int n_in,
                              void* d_out, int out_size)
{
    const float* query = (const float*)d_in[0];
    const float* key   = (const float*)d_in[1];
    const float* value = (const float*)d_in[2];
    const float* Wq    = (const float*)d_in[3];
    const float* bq    = (const float*)d_in[4];
    const float* Wk    = (const float*)d_in[5];
    const float* bk    = (const float*)d_in[6];
    const float* Wv    = (const float*)d_in[7];
    const float* bv    = (const float*)d_in[8];
    const float* Wo    = (const float*)d_in[9];
    const float* bo    = (const float*)d_in[10];
    const int*   mask  = (const int*)d_in[11];

    float* out_x = (float*)d_out;
    float* attn  = out_x + (size_t)MROWS * HID;

    float *qb, *kb, *vb, *ob;
    float *rq, *rk, *rv, *wq, *wk, *wv, *wo;
    cudaGetSymbolAddress((void**)&qb, g_Q);
    cudaGetSymbolAddress((void**)&kb, g_K);
    cudaGetSymbolAddress((void**)&vb, g_V);
    cudaGetSymbolAddress((void**)&ob, g_O);
    cudaGetSymbolAddress((void**)&rq, g_Rq);
    cudaGetSymbolAddress((void**)&rk, g_Rk);
    cudaGetSymbolAddress((void**)&rv, g_Rv);
    cudaGetSymbolAddress((void**)&wq, g_Wq);
    cudaGetSymbolAddress((void**)&wk, g_Wk);
    cudaGetSymbolAddress((void**)&wv, g_Wv);
    cudaGetSymbolAddress((void**)&wo, g_Wo);

    static int attr_done = 0;
    if (!attr_done){
        cudaFuncSetAttribute(qkv_proj_kernel,
            cudaFuncAttributeMaxDynamicSharedMemorySize, PROJ_SMEM_BYTES);
        cudaFuncSetAttribute(proj_kernel,
            cudaFuncAttributeMaxDynamicSharedMemorySize, PROJ_SMEM_BYTES);
        cudaFuncSetAttribute(fused_attn_kernel,
            cudaFuncAttributeMaxDynamicSharedMemorySize, FUSED_SMEM_BYTES);
        attr_done = 1;
    }

    // Pre-round GEMM operands to tf32 (RN) once.
    dim3 gract(MROWS*HID/(4*256), 1, 3);    // (8192,1,3)
    dim3 grw(HID*HID/(4*256), 1, 4);        // (1024,1,4)
    round_act_kernel<<<gract, 256>>>(query, key, value, rq, rk, rv);
    round_w_kernel<<<grw, 256>>>(Wq, Wk, Wv, Wo, wq, wk, wv, wo);

    dim3 gqkv(HID/TBN, MROWS/TBM, 3);   // (8, 64, 3)
    dim3 gproj(HID/TBN, MROWS/TBM);     // (8, 64)

    // Q/K/V projections (1/sqrt(64) folded into Q); outputs tf32-rounded
    qkv_proj_kernel<<<gqkv, 256, PROJ_SMEM_BYTES>>>(
        rq, rk, rv, wq, wk, wv, bq, bk, bv, qb, kb, vb);

    // Fused E = QK^T, softmax (writes attention to d_out), O = P V
    fused_attn_kernel<<<BHS/STRIPE, 512, FUSED_SMEM_BYTES>>>(attn, mask);

    // x = O Wo^T + bo (exact fp32 output)
    proj_kernel<<<gproj, 256, PROJ_SMEM_BYTES>>>(ob, wo, bo, 1.0f, out_x);
}

// round 12
// speedup vs baseline: 2.6992x; 2.6992x over previous
#include <cuda_runtime.h>
#include <cuda_fp16.h>
#include <mma.h>
#include <cstdint>

using namespace nvcuda;

#define HID    1024
#define NHEADS 16
#define HDIM   64
#define BATCH  8
#define SEQ    1024
#define MROWS  (BATCH*SEQ)        // 8192
#define BHS    (BATCH*NHEADS*SEQ) // 131072

// Scratch (device globals — no allocation allowed)
__device__ __half g_Qh[MROWS*HID];
__device__ __half g_Kh[MROWS*HID];
__device__ __half g_Vh[MROWS*HID];
__device__ __half g_Oh[MROWS*HID];
// fp16 copies of raw inputs / weights
__device__ __half g_Xq[MROWS*HID];
__device__ __half g_Xk[MROWS*HID];
__device__ __half g_Xv[MROWS*HID];
__device__ __half g_Wqh[HID*HID];
__device__ __half g_Wkh[HID*HID];
__device__ __half g_Wvh[HID*HID];
__device__ __half g_Woh[HID*HID];

// ---------------------------------------------------------------------------
// cp.async helpers
// ---------------------------------------------------------------------------
__device__ __forceinline__ void cp_async16(void* smem, const void* gmem){
    unsigned s = (unsigned)__cvta_generic_to_shared(smem);
    asm volatile("cp.async.cg.shared.global [%0], [%1], 16;\n" :: "r"(s), "l"(gmem));
}
#define CP_COMMIT()  asm volatile("cp.async.commit_group;\n" ::: "memory")
#define CP_WAIT0()   asm volatile("cp.async.wait_group 0;\n" ::: "memory")

// ---------------------------------------------------------------------------
// fp32 -> fp16 conversion kernels (8 elements per thread)
// ---------------------------------------------------------------------------
__device__ __forceinline__ void cvt8(const float* in, __half* out, size_t i){
    float4 v0 = *(const float4*)(in + i);
    float4 v1 = *(const float4*)(in + i + 4);
    __half2 h0 = __floats2half2_rn(v0.x, v0.y);
    __half2 h1 = __floats2half2_rn(v0.z, v0.w);
    __half2 h2 = __floats2half2_rn(v1.x, v1.y);
    __half2 h3 = __floats2half2_rn(v1.z, v1.w);
    uint4 u;
    u.x = *(unsigned*)&h0; u.y = *(unsigned*)&h1;
    u.z = *(unsigned*)&h2; u.w = *(unsigned*)&h3;
    *(uint4*)(out + i) = u;
}

__global__ void __launch_bounds__(256)
cvt_act_kernel(const float* __restrict__ a0, const float* __restrict__ a1,
               const float* __restrict__ a2,
               __half* __restrict__ o0, __half* __restrict__ o1,
               __half* __restrict__ o2)
{
    const int z = blockIdx.z;
    const float* in  = (z==0) ? a0 : (z==1) ? a1 : a2;
    __half*      out = (z==0) ? o0 : (z==1) ? o1 : o2;
    cvt8(in, out, ((size_t)blockIdx.x*256 + threadIdx.x)*8);
}

__global__ void __launch_bounds__(256)
cvt_w_kernel(const float* __restrict__ w0, const float* __restrict__ w1,
             const float* __restrict__ w2, const float* __restrict__ w3,
             __half* __restrict__ o0, __half* __restrict__ o1,
             __half* __restrict__ o2, __half* __restrict__ o3)
{
    const int z = blockIdx.z;
    const float* in  = (z==0) ? w0 : (z==1) ? w1 : (z==2) ? w2 : w3;
    __half*      out = (z==0) ? o0 : (z==1) ? o1 : (z==2) ? o2 : o3;
    cvt8(in, out, ((size_t)blockIdx.x*256 + threadIdx.x)*8);
}

// ===========================================================================
// fp16 projection: C[M,1024] = (A[M,1024] @ W[1024,1024]^T + bias) * scale
// 128x128x64 tiles, m16n16k16 HMMA, cp.async double-buffered half smem.
// Output: half to Ch (if non-null) else fp32 to Cf.
// ===========================================================================
#define TBM 128
#define TBN 128
#define TBK 64
#define LDTH 72                          // halves per smem row (144 B)
#define PT_TILE (TBM*LDTH*2)             // 18432 B per buffer
#define EPLD 132
#define PROJ_SMEM_BYTES (4*PT_TILE)      // 73728 (>= 128*132*4 epilogue)

__device__ __forceinline__
void proj_body_h(const __half* __restrict__ A, const __half* __restrict__ W,
                 const float* __restrict__ bias, float scale,
                 float* __restrict__ Cf, __half* __restrict__ Ch,
                 char* smem)
{
    char* sAb[2] = { smem,             smem + 2*PT_TILE };
    char* sBb[2] = { smem + PT_TILE,   smem + 3*PT_TILE };

    const int tid  = threadIdx.x;
    const int warp = tid >> 5;
    const int wm   = warp & 3;
    const int wn   = warp >> 2;
    const int m0   = blockIdx.y * TBM;
    const int n0   = blockIdx.x * TBN;

    wmma::fragment<wmma::accumulator,16,16,16,float> acc[2][4];
    #pragma unroll
    for (int mi=0;mi<2;mi++)
        #pragma unroll
        for (int ni=0;ni<4;ni++)
            wmma::fill_fragment(acc[mi][ni], 0.0f);

    // tile: 128 rows x 64 halves = 128 rows x 8 chunks(16B); 1024 chunks, 4/thread
    {
        #pragma unroll
        for (int p=0;p<4;p++){
            const int idx = tid + p*256;
            const int r   = idx >> 3;
            const int ch  = idx & 7;
            cp_async16(sAb[0] + r*144 + ch*16, A + (size_t)(m0 + r)*HID + ch*8);
            cp_async16(sBb[0] + r*144 + ch*16, W + (size_t)(n0 + r)*HID + ch*8);
        }
        CP_COMMIT();
    }

    const int NKT = HID / TBK;  // 16
    for (int kt=0; kt<NKT; kt++){
        CP_WAIT0();
        __syncthreads();
        if (kt+1 < NKT){
            const int k0 = (kt+1)*TBK;
            char* Ad = sAb[(kt+1)&1];
            char* Bd = sBb[(kt+1)&1];
            #pragma unroll
            for (int p=0;p<4;p++){
                const int idx = tid + p*256;
                const int r   = idx >> 3;
                const int ch  = idx & 7;
                cp_async16(Ad + r*144 + ch*16, A + (size_t)(m0 + r)*HID + k0 + ch*8);
                cp_async16(Bd + r*144 + ch*16, W + (size_t)(n0 + r)*HID + k0 + ch*8);
            }
            CP_COMMIT();
        }
        const __half* As = (const __half*)sAb[kt&1];
        const __half* Bs = (const __half*)sBb[kt&1];
        #pragma unroll
        for (int kk=0; kk<TBK; kk+=16){
            wmma::fragment<wmma::matrix_a,16,16,16,__half,wmma::row_major> af[2];
            wmma::fragment<wmma::matrix_b,16,16,16,__half,wmma::col_major> bf[4];
            #pragma unroll
            for (int mi=0;mi<2;mi++)
                wmma::load_matrix_sync(af[mi], As + (wm*32+mi*16)*LDTH + kk, LDTH);
            #pragma unroll
            for (int ni=0;ni<4;ni++)
                wmma::load_matrix_sync(bf[ni], Bs + (wn*64+ni*16)*LDTH + kk, LDTH);
            #pragma unroll
            for (int mi=0;mi<2;mi++)
                #pragma unroll
                for (int ni=0;ni<4;ni++)
                    wmma::mma_sync(acc[mi][ni], af[mi], bf[ni], acc[mi][ni]);
        }
    }

    // Epilogue via fp32 smem staging
    __syncthreads();
    float* ep = (float*)smem;
    #pragma unroll
    for (int mi=0;mi<2;mi++)
        #pragma unroll
        for (int ni=0;ni<4;ni++)
            wmma::store_matrix_sync(ep + (wm*32+mi*16)*EPLD + wn*64 + ni*16,
                                    acc[mi][ni], EPLD, wmma::mem_row_major);
    __syncthreads();
    {
        const int er  = tid >> 5;
        const int ec4 = (tid & 31) * 4;
        float4 bb = *(const float4*)(bias + n0 + ec4);
        #pragma unroll
        for (int p=0;p<16;p++){
            int r = p*8 + er;
            float4 v = *(float4*)(ep + r*EPLD + ec4);
            v.x = (v.x + bb.x) * scale;
            v.y = (v.y + bb.y) * scale;
            v.z = (v.z + bb.z) * scale;
            v.w = (v.w + bb.w) * scale;
            if (Ch){
                __half2 h0 = __floats2half2_rn(v.x, v.y);
                __half2 h1 = __floats2half2_rn(v.z, v.w);
                __half2* dst = (__half2*)(Ch + (size_t)(m0 + r)*HID + n0 + ec4);
                dst[0] = h0; dst[1] = h1;
            } else {
                *(float4*)(Cf + (size_t)(m0 + r)*HID + n0 + ec4) = v;
            }
        }
    }
}

// Merged Q/K/V projection: blockIdx.z selects which projection
__global__ void __launch_bounds__(256,2)
qkv_proj_kernel(const float* __restrict__ bq, const float* __restrict__ bk,
                const float* __restrict__ bv)
{
    extern __shared__ char smem[];
    const int z = blockIdx.z;
    const __half* A    = (z==0) ? g_Xq  : (z==1) ? g_Xk  : g_Xv;
    const __half* W    = (z==0) ? g_Wqh : (z==1) ? g_Wkh : g_Wvh;
    const float* bias  = (z==0) ? bq : (z==1) ? bk : bv;
    __half*      C     = (z==0) ? g_Qh : (z==1) ? g_Kh : g_Vh;
    const float scale  = (z==0) ? 0.125f : 1.0f;
    proj_body_h(A, W, bias, scale, nullptr, C, smem);
}

__global__ void __launch_bounds__(256,2)
out_proj_kernel(const float* __restrict__ bo, float* __restrict__ C)
{
    extern __shared__ char smem[];
    proj_body_h(g_Oh, g_Woh, bo, 1.0f, C, nullptr, smem);
}

// ===========================================================================
// Fused attention: per block = 32 query rows of one (b,h). 512 threads,
// two warp-groups of 8 warps with private double-buffered 64-row K/V chunks.
//   Phase 1: E = Q Kh^T (fp16 MMA, fp32 acc, E stripe in SMEM)
//   Phase 2: exact fp32 masked softmax; exact P -> gmem; half P in-place in SMEM
//   Phase 3: O = P V (fp16 MMA), k split across groups, fp32 smem reduction
// ===========================================================================
#define STRIPE 32
#define CH     64
#define NCHUNK (SEQ/CH)           // 16
#define LDE    1032               // fp32 stride of E rows
#define LDEH   (2*LDE)            // half stride when reusing Es as half
#define LDKH   72                 // halves per K/V smem row
#define LDO    68                 // fp32 O-reduce stride
#define CHBYTES (CH*144)          // 9216 B per K/V chunk buffer
// smem layout (bytes)
#define FS_ES   0
#define FS_OSR  (STRIPE*LDE*4)                    // 132096
#define FS_QS   (FS_OSR + STRIPE*LDO*4)           // 140800
#define FS_KVB  (FS_QS + STRIPE*144)              // 145408
#define FS_MS   (FS_KVB + 4*CHBYTES)              // 182272
#define FUSED_SMEM_BYTES (FS_MS + SEQ*4)          // 186368

__device__ __forceinline__ void bar_group(int grp){
    asm volatile("bar.sync %0, 256;" :: "r"(grp+1) : "memory");
}

__global__ void __launch_bounds__(512,1)
fused_attn_kernel(float* __restrict__ attn, const int* __restrict__ mask)
{
    extern __shared__ char smc[];
    float*  Es  = (float*)(smc + FS_ES);
    float*  Osr = (float*)(smc + FS_OSR);
    __half* Qsh = (__half*)(smc + FS_QS);
    char*   KVB = smc + FS_KVB;
    int*    Ms  = (int*)(smc + FS_MS);

    const int tid   = threadIdx.x;
    const int warp  = tid >> 5;
    const int lane  = tid & 31;
    const int grp   = tid >> 8;
    const int gwarp = warp & 7;
    const int gtid  = tid & 255;

    const int blk  = blockIdx.x;
    const int bh   = blk >> 5;
    const int strp = blk & 31;
    const int b    = bh >> 4;
    const int h    = bh & 15;
    const int m0   = strp * STRIPE;

    const __half* Qb = g_Qh + ((size_t)b*SEQ + m0)*HID + h*HDIM;
    const __half* Kb = g_Kh + (size_t)b*SEQ*HID + h*HDIM;
    const __half* Vb = g_Vh + (size_t)b*SEQ*HID + h*HDIM;

    char* mybuf[2] = { KVB + (grp*2)*CHBYTES, KVB + (grp*2+1)*CHBYTES };

    if (tid < 256)
        *(int4*)(Ms + tid*4) = *(const int4*)(mask + b*SEQ + tid*4);

    // Q stripe: 32 rows x 64 halves = 256 chunks(16B); loaded by tid<256
    if (tid < 256){
        const int r  = tid >> 3;
        const int ch = tid & 7;
        cp_async16((char*)Qsh + r*144 + ch*16, Qb + (size_t)r*HID + ch*8);
    }
    // group g prefetches K chunk c0 = g into its buf0 (64 rows x 8 chunks)
    {
        const __half* src = Kb + (size_t)(grp*CH)*HID;
        #pragma unroll
        for (int p=0;p<2;p++){
            const int idx = gtid + p*256;
            const int r   = idx >> 3;
            const int ch  = idx & 7;
            cp_async16(mybuf[0] + r*144 + ch*16, src + (size_t)r*HID + ch*8);
        }
        CP_COMMIT();
    }
    CP_WAIT0();
    __syncthreads();   // Q (cross-group) + mask + K0 visible

    // -------- Phase 1: QK^T --------
    const int wm = gwarp & 1;
    const int wn = gwarp >> 1;
    for (int ci=0; ci<NCHUNK/2; ci++){
        const int c = 2*ci + grp;
        CP_WAIT0();
        bar_group(grp);
        if (ci+1 < NCHUNK/2){
            const __half* src = Kb + (size_t)((c+2)*CH)*HID;
            char* dst = mybuf[(ci+1)&1];
            #pragma unroll
            for (int p=0;p<2;p++){
                const int idx = gtid + p*256;
                const int r   = idx >> 3;
                const int ch  = idx & 7;
                cp_async16(dst + r*144 + ch*16, src + (size_t)r*HID + ch*8);
            }
            CP_COMMIT();
        }
        const __half* Ks = (const __half*)mybuf[ci&1];
        wmma::fragment<wmma::accumulator,16,16,16,float> a0, a1;
        wmma::fill_fragment(a0, 0.0f);
        wmma::fill_fragment(a1, 0.0f);
        #pragma unroll
        for (int k=0;k<HDIM;k+=32){
            wmma::fragment<wmma::matrix_a,16,16,16,__half,wmma::row_major> af0, af1;
            wmma::fragment<wmma::matrix_b,16,16,16,__half,wmma::col_major> bf0, bf1;
            wmma::load_matrix_sync(af0, Qsh + (wm*16)*LDKH + k,      LDKH);
            wmma::load_matrix_sync(af1, Qsh + (wm*16)*LDKH + k + 16, LDKH);
            wmma::load_matrix_sync(bf0, Ks  + (wn*16)*LDKH + k,      LDKH);
            wmma::load_matrix_sync(bf1, Ks  + (wn*16)*LDKH + k + 16, LDKH);
            wmma::mma_sync(a0, af0, bf0, a0);
            wmma::mma_sync(a1, af1, bf1, a1);
        }
        #pragma unroll
        for (int t=0;t<a0.num_elements;t++) a0.x[t] += a1.x[t];
        wmma::store_matrix_sync(Es + (wm*16)*LDE + c*CH + wn*16, a0, LDE,
                                wmma::mem_row_major);
    }

    // prefetch first V chunk for this group into buf0
    {
        const __half* src = Vb + (size_t)(grp*8*CH)*HID;
        #pragma unroll
        for (int p=0;p<2;p++){
            const int idx = gtid + p*256;
            const int r   = idx >> 3;
            const int ch  = idx & 7;
            cp_async16(mybuf[0] + r*144 + ch*16, src + (size_t)r*HID + ch*8);
        }
        CP_COMMIT();
    }
    __syncthreads();   // E stripe complete

    // -------- Phase 2: exact masked softmax; P exact -> gmem, half -> smem ----
    __half* Ph = (__half*)Es;   // in-place: half row r occupies first 2KB of row r
    #pragma unroll
    for (int rr=0; rr<2; rr++){
        const int r = warp*2 + rr;
        float v[32];
        float mx = -1e30f;
        #pragma unroll
        for (int i=0;i<8;i++){
            float4 t  = *(float4*)(Es + r*LDE + i*128 + lane*4);
            int4   mk = *(const int4*)(Ms + i*128 + lane*4);
            t.x = (mk.x == 0) ? -1e10f : t.x;
            t.y = (mk.y == 0) ? -1e10f : t.y;
            t.z = (mk.z == 0) ? -1e10f : t.z;
            t.w = (mk.w == 0) ? -1e10f : t.w;
            v[i*4+0]=t.x; v[i*4+1]=t.y; v[i*4+2]=t.z; v[i*4+3]=t.w;
            mx = fmaxf(mx, fmaxf(fmaxf(t.x,t.y), fmaxf(t.z,t.w)));
        }
        #pragma unroll
        for (int o=16;o;o>>=1) mx = fmaxf(mx, __shfl_xor_sync(0xffffffffu, mx, o));
        float s = 0.0f;
        #pragma unroll
        for (int i=0;i<32;i++){ v[i] = __expf(v[i]-mx); s += v[i]; }
        #pragma unroll
        for (int o=16;o;o>>=1) s += __shfl_xor_sync(0xffffffffu, s, o);
        // all reads of this row are complete warp-wide (shfl barrier above)
        const float inv = 1.0f / s;
        float* arow = attn + ((size_t)bh*SEQ + m0 + r) * SEQ;
        #pragma unroll
        for (int i=0;i<8;i++){
            float4 p;
            p.x = v[i*4+0]*inv; p.y = v[i*4+1]*inv;
            p.z = v[i*4+2]*inv; p.w = v[i*4+3]*inv;
            *(float4*)(arow + i*128 + lane*4) = p;       // exact attention out
            __half2 h0 = __floats2half2_rn(p.x, p.y);
            __half2 h1 = __floats2half2_rn(p.z, p.w);
            __half2* dst = (__half2*)(Ph + (size_t)r*LDEH + i*128 + lane*4);
            dst[0] = h0; dst[1] = h1;
        }
    }
    __syncthreads();   // half P visible to all warps

    // -------- Phase 3: O = P V, k split across groups --------
    wmma::fragment<wmma::accumulator,16,16,16,float> o0, o1;
    wmma::fill_fragment(o0, 0.0f);
    wmma::fill_fragment(o1, 0.0f);
    const int pn = gwarp >> 1;

    for (int ci=0; ci<8; ci++){
        CP_WAIT0();
        bar_group(grp);
        if (ci+1 < 8){
            const __half* src = Vb + (size_t)(grp*8*CH + (ci+1)*CH)*HID;
            char* dst = mybuf[(ci+1)&1];
            #pragma unroll
            for (int p=0;p<2;p++){
                const int idx = gtid + p*256;
                const int r   = idx >> 3;
                const int ch  = idx & 7;
                cp_async16(dst + r*144 + ch*16, src + (size_t)r*HID + ch*8);
            }
            CP_COMMIT();
        }
        const __half* Vs = (const __half*)mybuf[ci&1];
        const int kbase = grp*8*CH + ci*CH;
        #pragma unroll
        for (int kk=0; kk<CH; kk+=32){
            wmma::fragment<wmma::matrix_a,16,16,16,__half,wmma::row_major> af0, af1;
            wmma::fragment<wmma::matrix_b,16,16,16,__half,wmma::row_major> bf0, bf1;
            wmma::load_matrix_sync(af0, Ph + (size_t)(wm*16)*LDEH + kbase + kk,      LDEH);
            wmma::load_matrix_sync(af1, Ph + (size_t)(wm*16)*LDEH + kbase + kk + 16, LDEH);
            wmma::load_matrix_sync(bf0, Vs + kk*LDKH + pn*16,        LDKH);
            wmma::load_matrix_sync(bf1, Vs + (kk+16)*LDKH + pn*16,   LDKH);
            wmma::mma_sync(o0, af0, bf0, o0);
            wmma::mma_sync(o1, af1, bf1, o1);
        }
    }
    #pragma unroll
    for (int t=0;t<o0.num_elements;t++) o0.x[t] += o1.x[t];

    // cross-group fp32 reduction in Osr, then half store to g_Oh
    if (grp == 1)
        wmma::store_matrix_sync(Osr + (wm*16)*LDO + pn*16, o0, LDO,
                                wmma::mem_row_major);
    __syncthreads();
    if (grp == 0){
        wmma::fragment<wmma::accumulator,16,16,16,float> part;
        wmma::load_matrix_sync(part, Osr + (wm*16)*LDO + pn*16, LDO,
                               wmma::mem_row_major);
        #pragma unroll
        for (int t=0;t<o0.num_elements;t++) o0.x[t] += part.x[t];
        wmma::store_matrix_sync(Osr + (wm*16)*LDO + pn*16, o0, LDO,
                                wmma::mem_row_major);
    }
    __syncthreads();
    if (tid < 256){
        const int r  = tid >> 3;          // 0..31
        const int c0 = (tid & 7) * 8;     // 0..56
        __half* dst = g_Oh + (size_t)(b*SEQ + m0 + r)*HID + h*HDIM + c0;
        const float* srcr = Osr + r*LDO + c0;
        __half2 h0 = __floats2half2_rn(srcr[0], srcr[1]);
        __half2 h1 = __floats2half2_rn(srcr[2], srcr[3]);
        __half2 h2 = __floats2half2_rn(srcr[4], srcr[5]);
        __half2 h3 = __floats2half2_rn(srcr[6], srcr[7]);
        uint4 u;
        u.x = *(unsigned*)&h0; u.y = *(unsigned*)&h1;
        u.z = *(unsigned*)&h2; u.w = *(unsigned*)&h3;
        *(uint4*)dst = u;
    }
}

// ---------------------------------------------------------------------------
extern "C" void kernel_launch(void* const* d_in, const int* in_sizes, int n_in,
                              void* d_out, int out_size)
{
    const float* query = (const float*)d_in[0];
    const float* key   = (const float*)d_in[1];
    const float* value = (const float*)d_in[2];
    const float* Wq    = (const float*)d_in[3];
    const float* bq    = (const float*)d_in[4];
    const float* Wk    = (const float*)d_in[5];
    const float* bk    = (const float*)d_in[6];
    const float* Wv    = (const float*)d_in[7];
    const float* bv    = (const float*)d_in[8];
    const float* Wo    = (const float*)d_in[9];
    const float* bo    = (const float*)d_in[10];
    const int*   mask  = (const int*)d_in[11];

    float* out_x = (float*)d_out;
    float* attn  = out_x + (size_t)MROWS * HID;

    __half *xq, *xk, *xv, *wqh, *wkh, *wvh, *woh;
    cudaGetSymbolAddress((void**)&xq, g_Xq);
    cudaGetSymbolAddress((void**)&xk, g_Xk);
    cudaGetSymbolAddress((void**)&xv, g_Xv);
    cudaGetSymbolAddress((void**)&wqh, g_Wqh);
    cudaGetSymbolAddress((void**)&wkh, g_Wkh);
    cudaGetSymbolAddress((void**)&wvh, g_Wvh);
    cudaGetSymbolAddress((void**)&woh, g_Woh);

    static int attr_done = 0;
    if (!attr_done){
        cudaFuncSetAttribute(qkv_proj_kernel,
            cudaFuncAttributeMaxDynamicSharedMemorySize, PROJ_SMEM_BYTES);
        cudaFuncSetAttribute(out_proj_kernel,
            cudaFuncAttributeMaxDynamicSharedMemorySize, PROJ_SMEM_BYTES);
        cudaFuncSetAttribute(fused_attn_kernel,
            cudaFuncAttributeMaxDynamicSharedMemorySize, FUSED_SMEM_BYTES);
        attr_done = 1;
    }

    // fp32 -> fp16 conversions (inputs + weights)
    dim3 gact(MROWS*HID/(256*8), 1, 3);   // (4096,1,3)
    dim3 gw(HID*HID/(256*8), 1, 4);       // (512,1,4)
    cvt_act_kernel<<<gact, 256>>>(query, key, value, xq, xk, xv);
    cvt_w_kernel<<<gw, 256>>>(Wq, Wk, Wv, Wo, wqh, wkh, wvh, woh);

    dim3 gqkv(HID/TBN, MROWS/TBM, 3);   // (8, 64, 3)
    dim3 gproj(HID/TBN, MROWS/TBM);     // (8, 64)

    // Q/K/V projections (1/sqrt(64) folded into Q); half outputs
    qkv_proj_kernel<<<gqkv, 256, PROJ_SMEM_BYTES>>>(bq, bk, bv);

    // Fused E = QK^T, softmax (exact attention to d_out), O = P V
    fused_attn_kernel<<<BHS/STRIPE, 512, FUSED_SMEM_BYTES>>>(attn, mask);

    // x = O Wo^T + bo (exact fp32 output)
    out_proj_kernel<<<gproj, 256, PROJ_SMEM_BYTES>>>(bo, out_x);
}